// round 2
// baseline (speedup 1.0000x reference)
#include <cuda_runtime.h>
#include <math.h>

// Problem constants (fixed by the reference)
#define NB 8
#define HH 8
#define DD 64
#define CC 64
#define LL 1024
#define MM 1024
#define BHN 64          // NB*HH
#define NCH 512         // HH*CC

// Scratch: logits stored TRANSPOSED: g_logitsT[bh][m][l]  (256 MB, bss)
__device__ float  g_logitsT[(size_t)BHN * MM * LL];
__device__ double g_hsum[HH], g_hsq[HH];
__device__ float  g_hscale[HH], g_hshift[HH];
__device__ double g_csum[NCH], g_csq[NCH];
__device__ float  g_cscale[NCH], g_cshift[NCH];

// ---------------------------------------------------------------------------
// K0: zero the atomic accumulators (must run every graph replay)
// ---------------------------------------------------------------------------
__global__ void k_init()
{
    int t = threadIdx.x;
    if (t < HH) { g_hsum[t] = 0.0; g_hsq[t] = 0.0; }
    if (t < NCH) { g_csum[t] = 0.0; g_csq[t] = 0.0; }
}

// ---------------------------------------------------------------------------
// K1: logitsT[bh][m][l] = sum_d K[bh][d][m] * Q[bh][d][l]
// Block tile 128(m) x 128(l), 256 threads, 8x8 microtile, k-chunk 16.
// Also accumulates per-head sum / sumsq (for BatchNorm2d) via double atomics.
// ---------------------------------------------------------------------------
__global__ void __launch_bounds__(256) k_gemm1(const float* __restrict__ q,
                                               const float* __restrict__ k)
{
    const int bh = blockIdx.z;
    const int m0 = blockIdx.y * 128;
    const int l0 = blockIdx.x * 128;

    __shared__ float Ks[16][128];
    __shared__ float Qs[16][128];
    __shared__ float rs[8], rss[8];

    const int t  = threadIdx.x;
    const int tx = t & 15;    // l dim
    const int ty = t >> 4;    // m dim
    const int lane = t & 31, wp = t >> 5;

    const float* __restrict__ kb = k + (size_t)bh * DD * MM;
    const float* __restrict__ qb = q + (size_t)bh * DD * LL;

    float acc[8][8];
#pragma unroll
    for (int i = 0; i < 8; i++)
#pragma unroll
        for (int j = 0; j < 8; j++) acc[i][j] = 0.f;

    for (int d0 = 0; d0 < DD; d0 += 16) {
#pragma unroll
        for (int it = 0; it < 2; it++) {
            int vdx = t + it * 256;          // 0..511
            int kk  = vdx >> 5;              // 0..15
            int c4  = (vdx & 31) << 2;       // 0..124
            *(float4*)&Ks[kk][c4] = *(const float4*)&kb[(size_t)(d0 + kk) * MM + m0 + c4];
            *(float4*)&Qs[kk][c4] = *(const float4*)&qb[(size_t)(d0 + kk) * LL + l0 + c4];
        }
        __syncthreads();

#pragma unroll
        for (int kk = 0; kk < 16; kk++) {
            float4 a0 = *(float4*)&Ks[kk][ty * 8];
            float4 a1 = *(float4*)&Ks[kk][ty * 8 + 4];
            float4 b0 = *(float4*)&Qs[kk][tx * 8];
            float4 b1 = *(float4*)&Qs[kk][tx * 8 + 4];
            float a[8] = {a0.x, a0.y, a0.z, a0.w, a1.x, a1.y, a1.z, a1.w};
            float b[8] = {b0.x, b0.y, b0.z, b0.w, b1.x, b1.y, b1.z, b1.w};
#pragma unroll
            for (int i = 0; i < 8; i++)
#pragma unroll
                for (int j = 0; j < 8; j++)
                    acc[i][j] = fmaf(a[i], b[j], acc[i][j]);
        }
        __syncthreads();
    }

    // per-head BN1 stats (sum, sumsq) over this tile
    float s = 0.f, ss = 0.f;
#pragma unroll
    for (int i = 0; i < 8; i++)
#pragma unroll
        for (int j = 0; j < 8; j++) { float x = acc[i][j]; s += x; ss = fmaf(x, x, ss); }
#pragma unroll
    for (int off = 16; off; off >>= 1) {
        s  += __shfl_down_sync(0xffffffffu, s,  off);
        ss += __shfl_down_sync(0xffffffffu, ss, off);
    }
    if (lane == 0) { rs[wp] = s; rss[wp] = ss; }
    __syncthreads();
    if (t == 0) {
        double S = 0.0, SS = 0.0;
#pragma unroll
        for (int w = 0; w < 8; w++) { S += (double)rs[w]; SS += (double)rss[w]; }
        atomicAdd(&g_hsum[bh & 7], S);
        atomicAdd(&g_hsq[bh & 7], SS);
    }

    // write transposed logits: row = m, col = l (coalesced along l)
    float* __restrict__ ob = g_logitsT + (size_t)bh * MM * LL;
#pragma unroll
    for (int i = 0; i < 8; i++) {
        size_t row = (size_t)(m0 + ty * 8 + i) * LL + l0 + tx * 8;
        float4 w0 = make_float4(acc[i][0], acc[i][1], acc[i][2], acc[i][3]);
        float4 w1 = make_float4(acc[i][4], acc[i][5], acc[i][6], acc[i][7]);
        *(float4*)&ob[row]     = w0;
        *(float4*)&ob[row + 4] = w1;
    }
}

// ---------------------------------------------------------------------------
// K2: per-head scale/shift from BN1 stats
// ---------------------------------------------------------------------------
__global__ void k_hstats(const float* __restrict__ gamma, const float* __restrict__ beta)
{
    int h = threadIdx.x;
    if (h < HH) {
        double n    = (double)NB * LL * MM;
        double mean = g_hsum[h] / n;
        double var  = g_hsq[h] / n - mean * mean;
        double sc   = (double)gamma[h] * rsqrt(var + 1e-3);
        g_hscale[h] = (float)sc;
        g_hshift[h] = (float)((double)beta[h] - mean * sc);
    }
}

// ---------------------------------------------------------------------------
// K4: rv[bh][c][l] = sum_m softmax_row(l) * V[bh][c][m]
// Softmax fused: A = exp(s*logit + t) computed at staging time; per-row Z
// accumulated in registers, divided out in the epilogue. Also accumulates
// per-channel BN2 stats. Block: all 64 c x 128 l; 256 threads, 4x8 microtile.
// ---------------------------------------------------------------------------
__global__ void __launch_bounds__(256) k_gemm2(const float* __restrict__ v,
                                               float* __restrict__ out)
{
    const int bh = blockIdx.y;
    const int l0 = blockIdx.x * 128;
    const int h  = bh & 7;
    const float sc = g_hscale[h];
    const float sh = g_hshift[h];

    __shared__ float As[16][132];   // [m-chunk][l], padded
    __shared__ float Vs[16][68];    // [m-chunk][c], padded
    __shared__ float red[8][132];
    __shared__ float Zinv[128];

    const int t    = threadIdx.x;
    const int lane = t & 31, wp = t >> 5;
    const int cy   = t >> 4;        // 0..15 -> c block of 4
    const int lx   = t & 15;        // 0..15 -> l block of 8
    const int cst  = (t & 3) << 2;  // V staging: m group
    const int cvc  = t >> 2;        // V staging: c index

    const float* __restrict__ A  = g_logitsT + (size_t)bh * MM * LL + l0;
    const float* __restrict__ vb = v + (size_t)bh * CC * MM;

    float acc[4][8];
#pragma unroll
    for (int i = 0; i < 4; i++)
#pragma unroll
        for (int j = 0; j < 8; j++) acc[i][j] = 0.f;
    float zp[4] = {0.f, 0.f, 0.f, 0.f};

    for (int m0 = 0; m0 < MM; m0 += 16) {
        // stage exp(A) chunk [16][128] -- direct layout, coalesced
#pragma unroll
        for (int it = 0; it < 2; it++) {
            int kk = wp + it * 8;
            float4 x = *(const float4*)&A[(size_t)(m0 + kk) * LL + lane * 4];
            float4 e;
            e.x = __expf(fminf(fmaf(x.x, sc, sh), 60.f));
            e.y = __expf(fminf(fmaf(x.y, sc, sh), 60.f));
            e.z = __expf(fminf(fmaf(x.z, sc, sh), 60.f));
            e.w = __expf(fminf(fmaf(x.w, sc, sh), 60.f));
            zp[0] += e.x; zp[1] += e.y; zp[2] += e.z; zp[3] += e.w;
            *(float4*)&As[kk][lane * 4] = e;
        }
        // stage V chunk transposed -> Vs[m][c]
        {
            float4 x = *(const float4*)&vb[(size_t)cvc * MM + m0 + cst];
            Vs[cst + 0][cvc] = x.x;
            Vs[cst + 1][cvc] = x.y;
            Vs[cst + 2][cvc] = x.z;
            Vs[cst + 3][cvc] = x.w;
        }
        __syncthreads();

#pragma unroll
        for (int kk = 0; kk < 16; kk++) {
            float4 vv = *(float4*)&Vs[kk][cy * 4];
            float4 a0 = *(float4*)&As[kk][lx * 8];
            float4 a1 = *(float4*)&As[kk][lx * 8 + 4];
            float va[4] = {vv.x, vv.y, vv.z, vv.w};
            float al[8] = {a0.x, a0.y, a0.z, a0.w, a1.x, a1.y, a1.z, a1.w};
#pragma unroll
            for (int i = 0; i < 4; i++)
#pragma unroll
                for (int j = 0; j < 8; j++)
                    acc[i][j] = fmaf(va[i], al[j], acc[i][j]);
        }
        __syncthreads();
    }

    // reduce row sums Z over the 8 warps
    *(float4*)&red[wp][lane * 4] = make_float4(zp[0], zp[1], zp[2], zp[3]);
    __syncthreads();
    if (t < 128) {
        float z = 0.f;
#pragma unroll
        for (int w = 0; w < 8; w++) z += red[w][t];
        Zinv[t] = 1.f / z;
    }
    __syncthreads();

    // epilogue: normalize, write, channel stats
    float csum[4] = {0.f, 0.f, 0.f, 0.f};
    float csq[4]  = {0.f, 0.f, 0.f, 0.f};
#pragma unroll
    for (int i = 0; i < 4; i++)
#pragma unroll
        for (int j = 0; j < 8; j++) {
            float r = acc[i][j] * Zinv[lx * 8 + j];
            acc[i][j] = r;
            csum[i] += r;
            csq[i]  = fmaf(r, r, csq[i]);
        }

    float* __restrict__ ob = out + (size_t)bh * CC * LL + l0;
#pragma unroll
    for (int i = 0; i < 4; i++) {
        size_t row = (size_t)(cy * 4 + i) * LL + lx * 8;
        *(float4*)&ob[row]     = make_float4(acc[i][0], acc[i][1], acc[i][2], acc[i][3]);
        *(float4*)&ob[row + 4] = make_float4(acc[i][4], acc[i][5], acc[i][6], acc[i][7]);
    }

    // reduce channel stats across the 16 lx threads (width-16 shuffle)
#pragma unroll
    for (int off = 8; off; off >>= 1)
#pragma unroll
        for (int i = 0; i < 4; i++) {
            csum[i] += __shfl_down_sync(0xffffffffu, csum[i], off, 16);
            csq[i]  += __shfl_down_sync(0xffffffffu, csq[i],  off, 16);
        }
    if (lx == 0) {
#pragma unroll
        for (int i = 0; i < 4; i++) {
            int ch = h * CC + cy * 4 + i;
            atomicAdd(&g_csum[ch], (double)csum[i]);
            atomicAdd(&g_csq[ch],  (double)csq[i]);
        }
    }
}

// ---------------------------------------------------------------------------
// K5: per-channel BN2 scale/shift
// ---------------------------------------------------------------------------
__global__ void k_cstats(const float* __restrict__ gv, const float* __restrict__ bv)
{
    int c = blockIdx.x * blockDim.x + threadIdx.x;
    if (c < NCH) {
        double n    = (double)NB * LL;
        double mean = g_csum[c] / n;
        double var  = g_csq[c] / n - mean * mean;
        double s    = (double)gv[c] * rsqrt(var + 1e-3);
        g_cscale[c] = (float)s;
        g_cshift[c] = (float)((double)bv[c] - mean * s);
    }
}

// ---------------------------------------------------------------------------
// K6: BN2 apply + exact GELU, in place on d_out
// ---------------------------------------------------------------------------
__global__ void k_gelu(float* __restrict__ out)
{
    size_t i = ((size_t)blockIdx.x * blockDim.x + threadIdx.x) * 4;
    int ch = (int)((i >> 10) & (NCH - 1));
    float s = g_cscale[ch], b = g_cshift[ch];
    float4 x = *(float4*)&out[i];
    float vx[4] = {x.x, x.y, x.z, x.w};
#pragma unroll
    for (int u = 0; u < 4; u++) {
        float v = fmaf(vx[u], s, b);
        vx[u] = 0.5f * v * (1.f + erff(v * 0.70710678118654752f));
    }
    *(float4*)&out[i] = make_float4(vx[0], vx[1], vx[2], vx[3]);
}

// ---------------------------------------------------------------------------
extern "C" void kernel_launch(void* const* d_in, const int* in_sizes, int n_in,
                              void* d_out, int out_size)
{
    const float* q  = (const float*)d_in[0];
    const float* k  = (const float*)d_in[1];
    const float* v  = (const float*)d_in[2];
    const float* gs = (const float*)d_in[3];
    const float* bs = (const float*)d_in[4];
    const float* gv = (const float*)d_in[5];
    const float* bv = (const float*)d_in[6];
    float* out = (float*)d_out;

    k_init<<<1, 512>>>();

    dim3 g1(LL / 128, MM / 128, BHN);      // (8, 8, 64)
    k_gemm1<<<g1, 256>>>(q, k);

    k_hstats<<<1, 32>>>(gs, bs);

    dim3 g2(LL / 128, BHN);                // (8, 64)
    k_gemm2<<<g2, 256>>>(v, out);

    k_cstats<<<1, 512>>>(gv, bv);

    int total4 = (NB * NCH * LL) / 4;      // 1,048,576 float4s
    k_gelu<<<total4 / 256, 256>>>(out);
}

// round 4
// speedup vs baseline: 1.1962x; 1.1962x over previous
#include <cuda_runtime.h>
#include <cuda_bf16.h>
#include <math.h>
#include <stdint.h>

// Problem constants
#define NB 8
#define HH 8
#define DD 64
#define CC 64
#define LL 1024
#define MM 1024
#define BHN 64
#define NCH 512

// Scratch: logits stored TRANSPOSED: g_logitsT[bh][m][l]
__device__ float  g_logitsT[(size_t)BHN * MM * LL];
__device__ double g_hsum[HH], g_hsq[HH];
__device__ float  g_hscale[HH], g_hshift[HH];
__device__ double g_csum[NCH], g_csq[NCH];
__device__ float  g_cscale[NCH], g_cshift[NCH];

// ===========================================================================
// mma.sync helpers (sm_80+ baseline PTX; assembles for sm_100 target)
// ===========================================================================
__device__ __forceinline__ uint32_t smem_u32(const void* p) {
    uint32_t a;
    asm("{ .reg .u64 t; cvta.to.shared.u64 t, %1; cvt.u32.u64 %0, t; }" : "=r"(a) : "l"(p));
    return a;
}
__device__ __forceinline__ void ldsm_x4_t(uint32_t& r0, uint32_t& r1, uint32_t& r2,
                                          uint32_t& r3, uint32_t addr) {
    asm volatile("ldmatrix.sync.aligned.m8n8.x4.trans.shared.b16 {%0,%1,%2,%3}, [%4];"
                 : "=r"(r0), "=r"(r1), "=r"(r2), "=r"(r3) : "r"(addr));
}
__device__ __forceinline__ void mma_bf16(float* c, uint32_t a0, uint32_t a1, uint32_t a2,
                                         uint32_t a3, uint32_t b0, uint32_t b1) {
    asm volatile("mma.sync.aligned.m16n8k16.row.col.f32.bf16.bf16.f32 "
                 "{%0,%1,%2,%3}, {%4,%5,%6,%7}, {%8,%9}, {%0,%1,%2,%3};"
                 : "+f"(c[0]), "+f"(c[1]), "+f"(c[2]), "+f"(c[3])
                 : "r"(a0), "r"(a1), "r"(a2), "r"(a3), "r"(b0), "r"(b1));
}

// smem row stride for bf16 operand arrays: 136 elems = 272 bytes
#define SWE 136
#define SWB 272
#define ARR_BYTES (64 * SWB)        // 17408 per array
#define OFF_AHI 0
#define OFF_ALO (ARR_BYTES)
#define OFF_BHI (2 * ARR_BYTES)
#define OFF_BLO (3 * ARR_BYTES)
#define SM1_DYN (4 * ARR_BYTES)     // 69632

// ---------------------------------------------------------------------------
// K0: zero accumulators
// ---------------------------------------------------------------------------
__global__ void k_init()
{
    int t = threadIdx.x;
    if (t < HH) { g_hsum[t] = 0.0; g_hsq[t] = 0.0; }
    if (t < NCH) { g_csum[t] = 0.0; g_csq[t] = 0.0; }
}

// ---------------------------------------------------------------------------
// K1 (HMMA): logitsT[m][l] = sum_d K[d][m]*Q[d][l], bf16 3-pass split.
// 128(m) x 128(l) tile, K=64 staged once. 8 warps, warp tile 64x32.
// ---------------------------------------------------------------------------
__global__ void __launch_bounds__(256, 2) k_gemm1t(const float* __restrict__ q,
                                                   const float* __restrict__ k)
{
    extern __shared__ char sm[];
    const uint32_t smb = smem_u32(sm);
    const int bh = blockIdx.z;
    const int m0 = blockIdx.y * 128;
    const int l0 = blockIdx.x * 128;
    const int t  = threadIdx.x;
    const int wid = t >> 5, lane = t & 31;

    __shared__ float rs[8], rss[8];

    // ---- stage K and Q tiles as bf16 hi/lo, layout [k-row][col], stride 136
    {
        const float* __restrict__ kb = k + (size_t)bh * DD * MM + m0;
        const float* __restrict__ qb = q + (size_t)bh * DD * LL + l0;
        const int rr = t >> 3;          // 0..31
        const int c8 = t & 7;           // 0..7
#pragma unroll
        for (int half = 0; half < 2; half++) {
            int r = rr + half * 32;     // k-row 0..63
#pragma unroll
            for (int ci = 0; ci < 4; ci++) {
                int c4 = c8 + ci * 8;   // float4 index 0..31
                float4 x = *(const float4*)&kb[(size_t)r * MM + c4 * 4];
                __nv_bfloat16 h0 = __float2bfloat16(x.x), h1 = __float2bfloat16(x.y);
                __nv_bfloat16 h2 = __float2bfloat16(x.z), h3 = __float2bfloat16(x.w);
                __nv_bfloat16 e0 = __float2bfloat16(x.x - __bfloat162float(h0));
                __nv_bfloat16 e1 = __float2bfloat16(x.y - __bfloat162float(h1));
                __nv_bfloat16 e2 = __float2bfloat16(x.z - __bfloat162float(h2));
                __nv_bfloat16 e3 = __float2bfloat16(x.w - __bfloat162float(h3));
                uint32_t byo = r * SWB + c4 * 8;
                *(uint2*)(sm + OFF_AHI + byo) = make_uint2(
                    (uint32_t)__bfloat16_as_ushort(h0) | ((uint32_t)__bfloat16_as_ushort(h1) << 16),
                    (uint32_t)__bfloat16_as_ushort(h2) | ((uint32_t)__bfloat16_as_ushort(h3) << 16));
                *(uint2*)(sm + OFF_ALO + byo) = make_uint2(
                    (uint32_t)__bfloat16_as_ushort(e0) | ((uint32_t)__bfloat16_as_ushort(e1) << 16),
                    (uint32_t)__bfloat16_as_ushort(e2) | ((uint32_t)__bfloat16_as_ushort(e3) << 16));
                float4 y = *(const float4*)&qb[(size_t)r * LL + c4 * 4];
                __nv_bfloat16 g0 = __float2bfloat16(y.x), g1 = __float2bfloat16(y.y);
                __nv_bfloat16 g2 = __float2bfloat16(y.z), g3 = __float2bfloat16(y.w);
                __nv_bfloat16 f0 = __float2bfloat16(y.x - __bfloat162float(g0));
                __nv_bfloat16 f1 = __float2bfloat16(y.y - __bfloat162float(g1));
                __nv_bfloat16 f2 = __float2bfloat16(y.z - __bfloat162float(g2));
                __nv_bfloat16 f3 = __float2bfloat16(y.w - __bfloat162float(g3));
                *(uint2*)(sm + OFF_BHI + byo) = make_uint2(
                    (uint32_t)__bfloat16_as_ushort(g0) | ((uint32_t)__bfloat16_as_ushort(g1) << 16),
                    (uint32_t)__bfloat16_as_ushort(g2) | ((uint32_t)__bfloat16_as_ushort(g3) << 16));
                *(uint2*)(sm + OFF_BLO + byo) = make_uint2(
                    (uint32_t)__bfloat16_as_ushort(f0) | ((uint32_t)__bfloat16_as_ushort(f1) << 16),
                    (uint32_t)__bfloat16_as_ushort(f2) | ((uint32_t)__bfloat16_as_ushort(f3) << 16));
            }
        }
    }
    __syncthreads();

    // ---- warp tiling: wm in {0,1} -> m offset, wn in {0..3} -> n offset
    const int m0w = (wid & 1) * 64;
    const int n0w = (wid >> 1) * 32;

    // lane-dependent ldmatrix address offsets (bytes)
    // A (x4.trans from [k][m]): groups -> (m0-7,k0-7),(m8-15,k0-7),(m0-7,k8-15),(m8-15,k8-15)
    const uint32_t offA = (uint32_t)(((lane & 7) + ((lane >> 4) & 1) * 8) * SWB
                                     + (m0w + ((lane >> 3) & 1) * 8) * 2);
    // B (x4.trans from [k][n]): groups -> (k0-7,n0-7),(k8-15,n0-7),(k0-7,n8-15),(k8-15,n8-15)
    const uint32_t offB = (uint32_t)(((lane & 7) + ((lane >> 3) & 1) * 8) * SWB
                                     + (n0w + (lane >> 4) * 8) * 2);

    float acc[4][4][4];
#pragma unroll
    for (int i = 0; i < 4; i++)
#pragma unroll
        for (int j = 0; j < 4; j++)
#pragma unroll
            for (int r = 0; r < 4; r++) acc[i][j][r] = 0.f;

#pragma unroll
    for (int pass = 0; pass < 3; pass++) {
        const uint32_t BA = smb + ((pass == 2) ? OFF_ALO : OFF_AHI);
        const uint32_t BB = smb + ((pass == 1) ? OFF_BLO : OFF_BHI);
#pragma unroll
        for (int ks = 0; ks < 4; ks++) {
            uint32_t a[4][4], b[2][4];
#pragma unroll
            for (int mi = 0; mi < 4; mi++)
                ldsm_x4_t(a[mi][0], a[mi][1], a[mi][2], a[mi][3],
                          BA + offA + ks * 16 * SWB + mi * 32);
#pragma unroll
            for (int nj = 0; nj < 2; nj++)
                ldsm_x4_t(b[nj][0], b[nj][1], b[nj][2], b[nj][3],
                          BB + offB + ks * 16 * SWB + nj * 32);
#pragma unroll
            for (int mi = 0; mi < 4; mi++) {
#pragma unroll
                for (int nj = 0; nj < 2; nj++) {
                    mma_bf16(acc[mi][nj * 2],     a[mi][0], a[mi][1], a[mi][2], a[mi][3],
                             b[nj][0], b[nj][1]);
                    mma_bf16(acc[mi][nj * 2 + 1], a[mi][0], a[mi][1], a[mi][2], a[mi][3],
                             b[nj][2], b[nj][3]);
                }
            }
        }
    }

    // ---- BN1 stats over accumulators
    float s = 0.f, ss = 0.f;
#pragma unroll
    for (int i = 0; i < 4; i++)
#pragma unroll
        for (int j = 0; j < 4; j++)
#pragma unroll
            for (int r = 0; r < 4; r++) {
                float x = acc[i][j][r];
                s += x; ss = fmaf(x, x, ss);
            }
#pragma unroll
    for (int off = 16; off; off >>= 1) {
        s  += __shfl_down_sync(0xffffffffu, s,  off);
        ss += __shfl_down_sync(0xffffffffu, ss, off);
    }
    if (lane == 0) { rs[wid] = s; rss[wid] = ss; }
    __syncthreads();
    if (t == 0) {
        double S = 0.0, SS = 0.0;
#pragma unroll
        for (int w = 0; w < 8; w++) { S += (double)rs[w]; SS += (double)rss[w]; }
        atomicAdd(&g_hsum[bh & 7], S);
        atomicAdd(&g_hsq[bh & 7], SS);
    }

    // ---- write logitsT: C fragment rows = m, cols = l
    float* __restrict__ ob = g_logitsT + (size_t)bh * MM * LL;
    const int cr = lane >> 2;       // row within atom
    const int cc = (lane & 3) * 2;  // col pair within atom
#pragma unroll
    for (int mi = 0; mi < 4; mi++) {
#pragma unroll
        for (int nj = 0; nj < 4; nj++) {
            size_t r0 = (size_t)(m0 + m0w + mi * 16 + cr) * LL + l0 + n0w + nj * 8 + cc;
            size_t r1 = r0 + 8 * LL;
            *(float2*)&ob[r0] = make_float2(acc[mi][nj][0], acc[mi][nj][1]);
            *(float2*)&ob[r1] = make_float2(acc[mi][nj][2], acc[mi][nj][3]);
        }
    }
}

// ---------------------------------------------------------------------------
// K2: per-head scale/shift
// ---------------------------------------------------------------------------
__global__ void k_hstats(const float* __restrict__ gamma, const float* __restrict__ beta)
{
    int h = threadIdx.x;
    if (h < HH) {
        double n    = (double)NB * LL * MM;
        double mean = g_hsum[h] / n;
        double var  = g_hsq[h] / n - mean * mean;
        double sc   = (double)gamma[h] * rsqrt(var + 1e-3);
        g_hscale[h] = (float)sc;
        g_hshift[h] = (float)((double)beta[h] - mean * sc);
    }
}

// ---------------------------------------------------------------------------
// K4: fused softmax + GEMM2 + BN2 stats. Double-buffered, 1 sync per chunk.
// ---------------------------------------------------------------------------
__global__ void __launch_bounds__(256) k_gemm2(const float* __restrict__ v,
                                               float* __restrict__ out)
{
    const int bh = blockIdx.y;
    const int l0 = blockIdx.x * 128;
    const int h  = bh & 7;
    const float sc = g_hscale[h];
    const float sh = g_hshift[h];

    __shared__ float As[2][16][132];
    __shared__ float Vs[2][16][68];
    __shared__ float red[8][132];
    __shared__ float Zinv[128];

    const int t    = threadIdx.x;
    const int lane = t & 31, wp = t >> 5;
    const int cy   = t >> 4;
    const int lx   = t & 15;
    const int cst  = (t & 3) << 2;
    const int cvc  = t >> 2;

    const float* __restrict__ A  = g_logitsT + (size_t)bh * MM * LL + l0;
    const float* __restrict__ vb = v + (size_t)bh * CC * MM;

    float acc[4][8];
#pragma unroll
    for (int i = 0; i < 4; i++)
#pragma unroll
        for (int j = 0; j < 8; j++) acc[i][j] = 0.f;
    float zp[4] = {0.f, 0.f, 0.f, 0.f};

    float4 ea0, ea1, vvr;

    // prolog: load+exp chunk 0
    {
        float4 x0 = *(const float4*)&A[(size_t)(wp) * LL + lane * 4];
        float4 x1 = *(const float4*)&A[(size_t)(wp + 8) * LL + lane * 4];
        ea0.x = __expf(fminf(fmaf(x0.x, sc, sh), 60.f));
        ea0.y = __expf(fminf(fmaf(x0.y, sc, sh), 60.f));
        ea0.z = __expf(fminf(fmaf(x0.z, sc, sh), 60.f));
        ea0.w = __expf(fminf(fmaf(x0.w, sc, sh), 60.f));
        ea1.x = __expf(fminf(fmaf(x1.x, sc, sh), 60.f));
        ea1.y = __expf(fminf(fmaf(x1.y, sc, sh), 60.f));
        ea1.z = __expf(fminf(fmaf(x1.z, sc, sh), 60.f));
        ea1.w = __expf(fminf(fmaf(x1.w, sc, sh), 60.f));
        zp[0] += ea0.x + ea1.x; zp[1] += ea0.y + ea1.y;
        zp[2] += ea0.z + ea1.z; zp[3] += ea0.w + ea1.w;
        vvr = *(const float4*)&vb[(size_t)cvc * MM + cst];
        *(float4*)&As[0][wp][lane * 4]     = ea0;
        *(float4*)&As[0][wp + 8][lane * 4] = ea1;
        Vs[0][cst + 0][cvc] = vvr.x; Vs[0][cst + 1][cvc] = vvr.y;
        Vs[0][cst + 2][cvc] = vvr.z; Vs[0][cst + 3][cvc] = vvr.w;
    }

    for (int it = 0; it < 64; it++) {
        const int buf = it & 1;
        if (it < 63) {
            const int m0 = (it + 1) * 16;
            float4 x0 = *(const float4*)&A[(size_t)(m0 + wp) * LL + lane * 4];
            float4 x1 = *(const float4*)&A[(size_t)(m0 + wp + 8) * LL + lane * 4];
            vvr = *(const float4*)&vb[(size_t)cvc * MM + m0 + cst];
            ea0.x = __expf(fminf(fmaf(x0.x, sc, sh), 60.f));
            ea0.y = __expf(fminf(fmaf(x0.y, sc, sh), 60.f));
            ea0.z = __expf(fminf(fmaf(x0.z, sc, sh), 60.f));
            ea0.w = __expf(fminf(fmaf(x0.w, sc, sh), 60.f));
            ea1.x = __expf(fminf(fmaf(x1.x, sc, sh), 60.f));
            ea1.y = __expf(fminf(fmaf(x1.y, sc, sh), 60.f));
            ea1.z = __expf(fminf(fmaf(x1.z, sc, sh), 60.f));
            ea1.w = __expf(fminf(fmaf(x1.w, sc, sh), 60.f));
            zp[0] += ea0.x + ea1.x; zp[1] += ea0.y + ea1.y;
            zp[2] += ea0.z + ea1.z; zp[3] += ea0.w + ea1.w;
        }
        __syncthreads();
        if (it < 63) {
            const int nb = buf ^ 1;
            *(float4*)&As[nb][wp][lane * 4]     = ea0;
            *(float4*)&As[nb][wp + 8][lane * 4] = ea1;
            Vs[nb][cst + 0][cvc] = vvr.x; Vs[nb][cst + 1][cvc] = vvr.y;
            Vs[nb][cst + 2][cvc] = vvr.z; Vs[nb][cst + 3][cvc] = vvr.w;
        }
#pragma unroll
        for (int kk = 0; kk < 16; kk++) {
            float4 vv = *(float4*)&Vs[buf][kk][cy * 4];
            float4 a0 = *(float4*)&As[buf][kk][lx * 8];
            float4 a1 = *(float4*)&As[buf][kk][lx * 8 + 4];
            float va[4] = {vv.x, vv.y, vv.z, vv.w};
            float al[8] = {a0.x, a0.y, a0.z, a0.w, a1.x, a1.y, a1.z, a1.w};
#pragma unroll
            for (int i = 0; i < 4; i++)
#pragma unroll
                for (int j = 0; j < 8; j++)
                    acc[i][j] = fmaf(va[i], al[j], acc[i][j]);
        }
    }
    __syncthreads();

    *(float4*)&red[wp][lane * 4] = make_float4(zp[0], zp[1], zp[2], zp[3]);
    __syncthreads();
    if (t < 128) {
        float z = 0.f;
#pragma unroll
        for (int w = 0; w < 8; w++) z += red[w][t];
        Zinv[t] = 1.f / z;
    }
    __syncthreads();

    float csum[4] = {0.f, 0.f, 0.f, 0.f};
    float csq[4]  = {0.f, 0.f, 0.f, 0.f};
#pragma unroll
    for (int i = 0; i < 4; i++)
#pragma unroll
        for (int j = 0; j < 8; j++) {
            float r = acc[i][j] * Zinv[lx * 8 + j];
            acc[i][j] = r;
            csum[i] += r;
            csq[i]  = fmaf(r, r, csq[i]);
        }

    float* __restrict__ ob = out + (size_t)bh * CC * LL + l0;
#pragma unroll
    for (int i = 0; i < 4; i++) {
        size_t row = (size_t)(cy * 4 + i) * LL + lx * 8;
        *(float4*)&ob[row]     = make_float4(acc[i][0], acc[i][1], acc[i][2], acc[i][3]);
        *(float4*)&ob[row + 4] = make_float4(acc[i][4], acc[i][5], acc[i][6], acc[i][7]);
    }

#pragma unroll
    for (int off = 8; off; off >>= 1)
#pragma unroll
        for (int i = 0; i < 4; i++) {
            csum[i] += __shfl_down_sync(0xffffffffu, csum[i], off, 16);
            csq[i]  += __shfl_down_sync(0xffffffffu, csq[i],  off, 16);
        }
    if (lx == 0) {
#pragma unroll
        for (int i = 0; i < 4; i++) {
            int ch = h * CC + cy * 4 + i;
            atomicAdd(&g_csum[ch], (double)csum[i]);
            atomicAdd(&g_csq[ch],  (double)csq[i]);
        }
    }
}

// ---------------------------------------------------------------------------
// K5: per-channel BN2 scale/shift
// ---------------------------------------------------------------------------
__global__ void k_cstats(const float* __restrict__ gv, const float* __restrict__ bv)
{
    int c = blockIdx.x * blockDim.x + threadIdx.x;
    if (c < NCH) {
        double n    = (double)NB * LL;
        double mean = g_csum[c] / n;
        double var  = g_csq[c] / n - mean * mean;
        double s    = (double)gv[c] * rsqrt(var + 1e-3);
        g_cscale[c] = (float)s;
        g_cshift[c] = (float)((double)bv[c] - mean * s);
    }
}

// ---------------------------------------------------------------------------
// K6: BN2 apply + exact GELU, in place
// ---------------------------------------------------------------------------
__global__ void k_gelu(float* __restrict__ out)
{
    size_t i = ((size_t)blockIdx.x * blockDim.x + threadIdx.x) * 4;
    int ch = (int)((i >> 10) & (NCH - 1));
    float s = g_cscale[ch], b = g_cshift[ch];
    float4 x = *(float4*)&out[i];
    float vx[4] = {x.x, x.y, x.z, x.w};
#pragma unroll
    for (int u = 0; u < 4; u++) {
        float v = fmaf(vx[u], s, b);
        vx[u] = 0.5f * v * (1.f + erff(v * 0.70710678118654752f));
    }
    *(float4*)&out[i] = make_float4(vx[0], vx[1], vx[2], vx[3]);
}

// ---------------------------------------------------------------------------
extern "C" void kernel_launch(void* const* d_in, const int* in_sizes, int n_in,
                              void* d_out, int out_size)
{
    const float* q  = (const float*)d_in[0];
    const float* k  = (const float*)d_in[1];
    const float* v  = (const float*)d_in[2];
    const float* gs = (const float*)d_in[3];
    const float* bs = (const float*)d_in[4];
    const float* gv = (const float*)d_in[5];
    const float* bv = (const float*)d_in[6];
    float* out = (float*)d_out;

    cudaFuncSetAttribute(k_gemm1t, cudaFuncAttributeMaxDynamicSharedMemorySize, SM1_DYN);

    k_init<<<1, 512>>>();

    dim3 g1(LL / 128, MM / 128, BHN);      // (8, 8, 64)
    k_gemm1t<<<g1, 256, SM1_DYN>>>(q, k);

    k_hstats<<<1, 32>>>(gs, bs);

    dim3 g2(LL / 128, BHN);                // (8, 64)
    k_gemm2<<<g2, 256>>>(v, out);

    k_cstats<<<1, 512>>>(gv, bv);

    int total4 = (NB * NCH * LL) / 4;
    k_gelu<<<total4 / 256, 256>>>(out);
}